// round 4
// baseline (speedup 1.0000x reference)
#include <cuda_runtime.h>
#include <math.h>
#include <stdint.h>

// ---------------------------------------------------------------------------
// HashEncoderHyFluid, R3: Morton-binned counting sort for gather locality.
// The encode kernel is at the L1tex wavefront floor (1 wf per distinct line
// per instruction). Sorting queries along an 18-bit Morton curve puts warp
// lanes in the same/nearby grid cells -> identical gather addresses share a
// wavefront (broadcast). Pipeline: zero-hist -> hist -> scan -> scatter ->
// encode(sorted, scatter-write to original slots).
// ---------------------------------------------------------------------------

#define CAP   (1 << 20)     // max queries supported by sort scratch (n = 1e6)
#define NBINS (1 << 18)     // 18-bit Morton key: x5 y5 z4 t4

__device__ float4   g_sorted[CAP];
__device__ unsigned g_oidx[CAP];
__device__ unsigned g_hist[NBINS];

struct Level {
    float    rf0, rf1, rf2, rf3;
    unsigned s1, s2, s3;           // dense strides
    unsigned mask;                 // size-1 (hashed pow2)
    unsigned size;
    int      offset;               // float offset into hash_table
    int      mode;                 // 0 dense, 1 hash+mask, 2 hash+mod
};
struct KConfig { Level lv[16]; };

#define HPRIME1 2654435761u
#define HPRIME2 805459861u
#define HPRIME3 3674653429u

// ---------------- sort kernels ----------------

__device__ __forceinline__ unsigned morton_key(float4 X)
{
    unsigned kx = (unsigned)(X.x * 32.f); if (kx > 31u) kx = 31u;
    unsigned ky = (unsigned)(X.y * 32.f); if (ky > 31u) ky = 31u;
    unsigned kz = (unsigned)(X.z * 16.f); if (kz > 15u) kz = 15u;
    unsigned kt = (unsigned)(X.w * 16.f); if (kt > 15u) kt = 15u;
    unsigned key = 0;
    #pragma unroll
    for (int b = 4; b >= 0; --b) {
        key = (key << 1) | ((kx >> b) & 1u);
        key = (key << 1) | ((ky >> b) & 1u);
        if (b < 4) {
            key = (key << 1) | ((kz >> b) & 1u);
            key = (key << 1) | ((kt >> b) & 1u);
        }
    }
    return key;   // 18 bits
}

__global__ void zero_hist_kernel()
{
    int i = blockIdx.x * blockDim.x + threadIdx.x;
    if (i < NBINS) g_hist[i] = 0u;
}

__global__ void hist_kernel(const float4* __restrict__ xyzt, int n)
{
    int i = blockIdx.x * blockDim.x + threadIdx.x;
    if (i >= n) return;
    atomicAdd(&g_hist[morton_key(xyzt[i])], 1u);
}

// single block, 1024 threads; each thread owns NBINS/1024 = 256 bins
__global__ __launch_bounds__(1024)
void scan_kernel()
{
    __shared__ unsigned sh[1024];
    const int t = threadIdx.x;
    const int per = NBINS / 1024;
    const unsigned base = (unsigned)t * per;

    unsigned sum = 0;
    for (int i = 0; i < per; ++i) sum += g_hist[base + i];
    sh[t] = sum;
    __syncthreads();
    // inclusive Hillis-Steele scan over 1024 partials
    for (int off = 1; off < 1024; off <<= 1) {
        unsigned v = (t >= off) ? sh[t - off] : 0u;
        __syncthreads();
        sh[t] += v;
        __syncthreads();
    }
    unsigned run = sh[t] - sum;    // exclusive prefix of this thread's range
    for (int i = 0; i < per; ++i) {
        unsigned h = g_hist[base + i];
        g_hist[base + i] = run;    // exclusive bin offset
        run += h;
    }
}

__global__ void scatter_kernel(const float4* __restrict__ xyzt, int n)
{
    int i = blockIdx.x * blockDim.x + threadIdx.x;
    if (i >= n) return;
    float4 X = xyzt[i];
    unsigned pos = atomicAdd(&g_hist[morton_key(X)], 1u);
    g_sorted[pos] = X;
    g_oidx[pos]   = (unsigned)i;
}

// ---------------- encode ----------------

__device__ __forceinline__ void acc_pair128(const float2* __restrict__ t2,
                                            unsigned i0, float w0, float w1,
                                            float& a0, float& a1)
{
    unsigned m = i0 & ~1u;
    float4 f = __ldg(reinterpret_cast<const float4*>(t2 + m));
    bool odd = (i0 & 1u);
    float c0x = odd ? f.z : f.x, c0y = odd ? f.w : f.y;
    float c1x = odd ? f.x : f.z, c1y = odd ? f.y : f.w;
    a0 += w0 * c0x + w1 * c1x;
    a1 += w0 * c0y + w1 * c1y;
}

__device__ __forceinline__ void encode_level(const float4& X,
                                             const Level& L,
                                             const float* __restrict__ tab,
                                             float& a0, float& a1)
{
    float px = X.x * L.rf0, py = X.y * L.rf1, pz = X.z * L.rf2, pt = X.w * L.rf3;
    float gx = floorf(px),  gy = floorf(py),  gz = floorf(pz),  gt = floorf(pt);
    float fx = px - gx,     fy = py - gy,     fz = pz - gz,     ft = pt - gt;
    unsigned cx = (unsigned)(int)gx, cy = (unsigned)(int)gy;
    unsigned cz = (unsigned)(int)gz, ct = (unsigned)(int)gt;

    float wx0 = 1.f - fx, wy0 = 1.f - fy, wz0 = 1.f - fz, wt0 = 1.f - ft;
    float wxy[4], wzt[4];
    wxy[0] = wx0 * wy0;  wxy[1] = fx * wy0;  wxy[2] = wx0 * fy;  wxy[3] = fx * fy;
    wzt[0] = wz0 * wt0;  wzt[1] = fz * wt0;  wzt[2] = wz0 * ft;  wzt[3] = fz * ft;

    const float2* t2 = reinterpret_cast<const float2*>(tab) + (L.offset >> 1);
    a0 = 0.f; a1 = 0.f;

    if (L.mode == 0) {
        unsigned bxy = cx + cy * L.s1;
        unsigned ixy0[2] = { bxy, bxy + L.s1 };
        unsigned bzt = cz * L.s2 + ct * L.s3;
        unsigned izt[4] = { bzt, bzt + L.s2, bzt + L.s3, bzt + L.s2 + L.s3 };
        #pragma unroll
        for (int j = 0; j < 4; ++j) {
            #pragma unroll
            for (int b = 0; b < 2; ++b) {
                unsigned i0 = ixy0[b] + izt[j];
                float w0 = wxy[2 * b]     * wzt[j];
                float w1 = wxy[2 * b + 1] * wzt[j];
                if ((i0 & 1u) == 0u) {
                    acc_pair128(t2, i0, w0, w1, a0, a1);
                } else {
                    float2 f0 = __ldg(t2 + i0);
                    float2 f1 = __ldg(t2 + i0 + 1u);
                    a0 += w0 * f0.x + w1 * f1.x;
                    a1 += w0 * f0.y + w1 * f1.y;
                }
            }
        }
    } else {
        unsigned hy = cy * HPRIME1, hz = cz * HPRIME2, ht = ct * HPRIME3;
        unsigned msk = L.mask;
        unsigned rxy0[2] = { hy, hy + HPRIME1 };
        unsigned izt[4] = { hz ^ ht, (hz + HPRIME2) ^ ht,
                            hz ^ (ht + HPRIME3), (hz + HPRIME2) ^ (ht + HPRIME3) };
        if (L.mode == 1) {
            if ((cx & 1u) == 0u) {
                #pragma unroll
                for (int j = 0; j < 4; ++j) {
                    #pragma unroll
                    for (int b = 0; b < 2; ++b) {
                        unsigned i0 = (cx ^ rxy0[b] ^ izt[j]) & msk;
                        acc_pair128(t2, i0,
                                    wxy[2 * b] * wzt[j], wxy[2 * b + 1] * wzt[j],
                                    a0, a1);
                    }
                }
            } else {
                unsigned cx1 = cx + 1u;
                #pragma unroll
                for (int j = 0; j < 4; ++j) {
                    #pragma unroll
                    for (int b = 0; b < 2; ++b) {
                        unsigned r = rxy0[b] ^ izt[j];
                        unsigned i0 = (cx  ^ r) & msk;
                        unsigned i1 = (cx1 ^ r) & msk;
                        float w0 = wxy[2 * b]     * wzt[j];
                        float w1 = wxy[2 * b + 1] * wzt[j];
                        float2 f0 = __ldg(t2 + i0);
                        float2 f1 = __ldg(t2 + i1);
                        a0 += w0 * f0.x + w1 * f1.x;
                        a1 += w0 * f0.y + w1 * f1.y;
                    }
                }
            }
        } else {
            unsigned sz = L.size, cx1 = cx + 1u;
            #pragma unroll
            for (int j = 0; j < 4; ++j) {
                #pragma unroll
                for (int b = 0; b < 2; ++b) {
                    unsigned r = rxy0[b] ^ izt[j];
                    unsigned i0 = (cx  ^ r) % sz;
                    unsigned i1 = (cx1 ^ r) % sz;
                    float w0 = wxy[2 * b]     * wzt[j];
                    float w1 = wxy[2 * b + 1] * wzt[j];
                    float2 f0 = __ldg(t2 + i0);
                    float2 f1 = __ldg(t2 + i1);
                    a0 += w0 * f0.x + w1 * f1.x;
                    a1 += w0 * f0.y + w1 * f1.y;
                }
            }
        }
    }
}

template <bool SORTED>
__global__ __launch_bounds__(256)
void hashenc_kernel(const float4* __restrict__ coords,
                    const float*  __restrict__ tab,
                    float*        __restrict__ out,
                    KConfig cfg, int n)
{
    int q = blockIdx.x * 256 + threadIdx.x;
    if (q >= n) return;

    float4 X = SORTED ? g_sorted[q] : coords[q];
    unsigned oq = SORTED ? g_oidx[q] : (unsigned)q;
    float4* o4 = reinterpret_cast<float4*>(out + (size_t)oq * 32);

    #pragma unroll 1
    for (int k = 0; k < 8; ++k) {
        float a0, a1, b0, b1;
        encode_level(X, cfg.lv[2 * k],     tab, a0, a1);
        encode_level(X, cfg.lv[2 * k + 1], tab, b0, b1);
        o4[k] = make_float4(a0, a1, b0, b1);
    }
}

// ---------------------------------------------------------------------------
// Host-side config: mirrors reference build_config() op-for-op in float64.
// ---------------------------------------------------------------------------
static KConfig build_cfg_host()
{
    const double minr[4] = {16.0, 16.0, 16.0, 16.0};
    const double maxr[4] = {256.0, 256.0, 256.0, 128.0};
    const long long MAXP = 524288; // 2^19

    double b[4];
    for (int d = 0; d < 4; ++d)
        b[d] = exp((log(maxr[d]) - log(minr[d])) / 15.0);

    KConfig cfg;
    long long total = 0;
    for (int s = 0; s < 16; ++s) {
        long long res[4];
        for (int d = 0; d < 4; ++d)
            res[d] = (long long)ceil(minr[d] * pow(b[d], (double)s));
        long long raw = (res[0] + 1) * (res[1] + 1) * (res[2] + 1) * (res[3] + 1);
        long long p = (raw % 8 == 0) ? raw : ((raw + 7) / 8) * 8;
        if (p > MAXP) p = MAXP;
        int dense = (raw <= p) ? 1 : 0;

        Level& L = cfg.lv[s];
        L.rf0 = (float)res[0]; L.rf1 = (float)res[1];
        L.rf2 = (float)res[2]; L.rf3 = (float)res[3];
        L.s1 = (unsigned)(res[0] + 1);
        L.s2 = (unsigned)((res[0] + 1) * (res[1] + 1));
        L.s3 = (unsigned)((res[0] + 1) * (res[1] + 1) * (res[2] + 1));
        L.size = (unsigned)p;
        L.mask = (unsigned)(p - 1);
        L.offset = (int)total;
        if (dense)                      L.mode = 0;
        else if ((p & (p - 1)) == 0)    L.mode = 1;
        else                            L.mode = 2;
        total += p * 2;  // F = 2
    }
    return cfg;
}

extern "C" void kernel_launch(void* const* d_in, const int* in_sizes, int n_in,
                              void* d_out, int out_size)
{
    static KConfig cfg = build_cfg_host();

    const float4* xyzt = (const float4*)d_in[0];
    const float*  tab  = (const float*)d_in[1];
    float*        out  = (float*)d_out;

    int n = in_sizes[0] / 4;
    int blocks = (n + 255) / 256;

    if (n <= CAP) {
        zero_hist_kernel<<<(NBINS + 1023) / 1024, 1024>>>();
        hist_kernel<<<blocks, 256>>>(xyzt, n);
        scan_kernel<<<1, 1024>>>();
        scatter_kernel<<<blocks, 256>>>(xyzt, n);
        hashenc_kernel<true><<<blocks, 256>>>(xyzt, tab, out, cfg, n);
    } else {
        hashenc_kernel<false><<<blocks, 256>>>(xyzt, tab, out, cfg, n);
    }
}